// round 3
// baseline (speedup 1.0000x reference)
#include <cuda_runtime.h>
#include <cuda_bf16.h>
#include <math.h>

// Shapes (fixed for this problem)
//   x:            (4, 256, 64, 64)  fp32
//   conv_offset_w:(27, 256, 3, 3)   fp32
//   conv_offset_b:(27,)             fp32
//   dcn_weight:   (256, 256, 3, 3)  fp32
//   out:          (4, 256, 64, 64)  fp32
//
// Pipeline:
//   K1 conv_offset  -> g_om   [4][27][64][64]
//   K2 permute      -> g_wperm[k=kk*256+c][o]           (2304 x 256)
//   K3 sample       -> g_valT [k=kk*256+c][m=n*4096+p]  (2304 x 16384)
//   K4 sgemm        -> out[n][o][p] = sum_k valT[k][m] * wperm[k][o]

#define NN 4
#define CC 256
#define HH 64
#define WW 64
#define OC 256
#define KDIM 2304          // 9 * 256
#define MDIM 16384         // 4 * 64 * 64

__device__ float g_om[NN * 27 * HH * WW];            // 1.77 MB
__device__ float g_wperm[KDIM * OC];                 // 2.36 MB
__device__ float g_valT[(size_t)KDIM * MDIM];        // 151 MB

// ---------------------------------------------------------------------------
// K1: offset conv. grid (64 y, 4 n), 256 threads = 64 pixels x 4 channel-groups
// ---------------------------------------------------------------------------
__global__ __launch_bounds__(256) void conv_offset_kernel(
    const float* __restrict__ x, const float* __restrict__ w,
    const float* __restrict__ b)
{
    int y = blockIdx.x, n = blockIdx.y;
    int t = threadIdx.x;
    int p = t & 63, g = t >> 6;

    __shared__ __align__(16) float sm[6912];
    float* xs = sm;         // [4][3][66] = 792 (padded region to 800)
    float* ws = sm + 800;   // [4][27][12] = 1296

    float acc[27];
#pragma unroll
    for (int oc = 0; oc < 27; oc++) acc[oc] = 0.f;

    for (int i = 0; i < 64; i++) {
        // stage x rows y-1..y+1 for the 4 channels {i, 64+i, 128+i, 192+i}
        for (int idx = t; idx < 792; idx += 256) {
            int gg = idx / 198, rem = idx - gg * 198;
            int r = rem / 66, j = rem - r * 66;
            int yy = y + r - 1, xx = j - 1;
            float v = 0.f;
            if (yy >= 0 && yy < HH && xx >= 0 && xx < WW)
                v = x[(((size_t)(n * CC + gg * 64 + i) * HH) + yy) * WW + xx];
            xs[(gg * 3 + r) * 66 + j] = v;
        }
        // stage weights for those channels: [g][oc][12] (9 used, 12 for f4 align)
        for (int idx = t; idx < 972; idx += 256) {
            int gg = idx / 243, rem = idx - gg * 243;
            int oc = rem / 9, kq = rem - oc * 9;
            ws[(gg * 27 + oc) * 12 + kq] = w[(oc * CC + gg * 64 + i) * 9 + kq];
        }
        __syncthreads();

        float tv[9];
#pragma unroll
        for (int r = 0; r < 3; r++)
#pragma unroll
            for (int s = 0; s < 3; s++)
                tv[r * 3 + s] = xs[(g * 3 + r) * 66 + p + s];

        const float4* wsg = (const float4*)(ws + g * 27 * 12);
#pragma unroll
        for (int oc = 0; oc < 27; oc++) {
            float4 w0 = wsg[oc * 3 + 0];
            float4 w1 = wsg[oc * 3 + 1];
            float  w8 = ws[(g * 27 + oc) * 12 + 8];
            acc[oc] += tv[0] * w0.x + tv[1] * w0.y + tv[2] * w0.z + tv[3] * w0.w
                     + tv[4] * w1.x + tv[5] * w1.y + tv[6] * w1.z + tv[7] * w1.w
                     + tv[8] * w8;
        }
        __syncthreads();
    }

    // cross-group reduction through smem (aliases xs/ws, safe after sync)
    float* red = sm;  // [4*64][27] = 6912
#pragma unroll
    for (int oc = 0; oc < 27; oc++) red[(g * 64 + p) * 27 + oc] = acc[oc];
    __syncthreads();
    for (int idx = t; idx < 1728; idx += 256) {
        int p2 = idx / 27, oc = idx - p2 * 27;
        float s = red[p2 * 27 + oc] + red[(64 + p2) * 27 + oc]
                + red[(128 + p2) * 27 + oc] + red[(192 + p2) * 27 + oc] + b[oc];
        g_om[(((size_t)n * 27 + oc) * HH + y) * WW + p2] = s;
    }
}

// ---------------------------------------------------------------------------
// K2: permute dcn_weight (o,c,kk) -> wperm[k=kk*256+c][o]
// ---------------------------------------------------------------------------
__global__ __launch_bounds__(256) void permute_w_kernel(const float* __restrict__ dw)
{
    int t = blockIdx.x * 256 + threadIdx.x;   // t = k*256 + o
    int o = t & 255;
    int k = t >> 8;
    int c = k & 255;
    int kk = k >> 8;
    g_wperm[t] = dw[(o * CC + c) * 9 + kk];
}

// ---------------------------------------------------------------------------
// K3: deformable bilinear sampling -> g_valT[k][m]
// grid (64 y, 4 n), 256 threads = 64 pixels x 4 channel-groups
// ---------------------------------------------------------------------------
__global__ __launch_bounds__(256) void sample_kernel(const float* __restrict__ x)
{
    int y = blockIdx.x, n = blockIdx.y;
    int t = threadIdx.x;

    __shared__ __align__(16) int   soff[576][4];
    __shared__ __align__(16) float swt[576][4];

    // Phase A: per (pixel, kk) tap metadata: 4 clamped tap offsets + 4
    // mask-folded bilinear weights (0 for out-of-image taps).
    for (int idx = t; idx < 576; idx += 256) {
        int p = idx / 9, kk = idx - p * 9;
        const float* omn = g_om + (size_t)n * 27 * 4096 + y * 64 + p;
        float oy = omn[(size_t)(2 * kk) * 4096];
        float ox = omn[(size_t)(2 * kk + 1) * 4096];
        float mv = omn[(size_t)(18 + kk) * 4096];
        float m  = 1.f / (1.f + __expf(-mv));

        float py = (float)(y + kk / 3) + oy;          // base(y+1) + inner(ky-1)
        float px = (float)(p + (kk % 3)) + ox;        // base(p+1) + inner(kx-1)
        py = fminf(fmaxf(py, 0.f), 65.f);
        px = fminf(fmaxf(px, 0.f), 65.f);
        float fy = floorf(py), fx = floorf(px);
        int y1 = (int)fy, x1 = (int)fx;
        float ly = py - fy, lx = px - fx;
        float hy = 1.f - ly, hx = 1.f - lx;
        float wt0 = hy * hx, wt1 = hy * lx, wt2 = ly * hx, wt3 = ly * lx;

#pragma unroll
        for (int q = 0; q < 4; q++) {
            int Y = y1 + (q >> 1);
            int X = x1 + (q & 1);
            bool valid = (Y >= 1 && Y <= 64 && X >= 1 && X <= 64);
            int Yc = min(max(Y, 1), 64), Xc = min(max(X, 1), 64);
            float wq = (q == 0) ? wt0 : (q == 1) ? wt1 : (q == 2) ? wt2 : wt3;
            soff[idx][q] = (Yc - 1) * 64 + (Xc - 1);
            swt[idx][q]  = valid ? wq * m : 0.f;
        }
    }
    __syncthreads();

    // Phase B: lanes over pixels (coalesced loads AND stores); metadata hoisted
    // to registers (channel-independent).
    int p = t & 63, g = t >> 6;
    int   ro[36];
    float rw[36];
#pragma unroll
    for (int kk = 0; kk < 9; kk++) {
        int4   o4 = *(const int4*)  &soff[p * 9 + kk][0];
        float4 w4 = *(const float4*)&swt [p * 9 + kk][0];
        ro[kk * 4 + 0] = o4.x; ro[kk * 4 + 1] = o4.y;
        ro[kk * 4 + 2] = o4.z; ro[kk * 4 + 3] = o4.w;
        rw[kk * 4 + 0] = w4.x; rw[kk * 4 + 1] = w4.y;
        rw[kk * 4 + 2] = w4.z; rw[kk * 4 + 3] = w4.w;
    }

    size_t mbase = (size_t)n * 4096 + (size_t)y * 64 + p;
    for (int j = 0; j < 64; j++) {
        int c = g * 64 + j;
        const float* xb = x + ((size_t)(n * CC + c)) * 4096;
        float* vb = g_valT + (size_t)c * MDIM + mbase;
#pragma unroll
        for (int kk = 0; kk < 9; kk++) {
            float v = rw[kk * 4 + 0] * __ldg(&xb[ro[kk * 4 + 0]])
                    + rw[kk * 4 + 1] * __ldg(&xb[ro[kk * 4 + 1]])
                    + rw[kk * 4 + 2] * __ldg(&xb[ro[kk * 4 + 2]])
                    + rw[kk * 4 + 3] * __ldg(&xb[ro[kk * 4 + 3]]);
            vb[(size_t)kk * 256 * MDIM] = v;
        }
    }
}

// ---------------------------------------------------------------------------
// K4: SGEMM  C[m][o] = sum_k valT[k][m] * wperm[k][o]
// BM=128, BN=64, BK=16, 256 threads, 8x4 micro-tile
// ---------------------------------------------------------------------------
__global__ __launch_bounds__(256) void sgemm_kernel(float* __restrict__ out)
{
    __shared__ __align__(16) float As[16][128];
    __shared__ __align__(16) float Bs[16][64];

    int t = threadIdx.x;
    int m0 = blockIdx.x * 128, o0 = blockIdx.y * 64;
    int tm = t >> 4, tn = t & 15;

    float acc[8][4];
#pragma unroll
    for (int i = 0; i < 8; i++)
#pragma unroll
        for (int j = 0; j < 4; j++) acc[i][j] = 0.f;

    int ar0 = t >> 5;            // rows 0..7
    int ac  = (t & 31) * 4;
    int ar1 = ar0 + 8;           // rows 8..15
    int br  = t >> 4;            // 0..15
    int bc  = (t & 15) * 4;

    for (int k0 = 0; k0 < KDIM; k0 += 16) {
        *(float4*)&As[ar0][ac] = *(const float4*)&g_valT[(size_t)(k0 + ar0) * MDIM + m0 + ac];
        *(float4*)&As[ar1][ac] = *(const float4*)&g_valT[(size_t)(k0 + ar1) * MDIM + m0 + ac];
        *(float4*)&Bs[br][bc]  = *(const float4*)&g_wperm[(size_t)(k0 + br) * OC + o0 + bc];
        __syncthreads();
#pragma unroll
        for (int kk = 0; kk < 16; kk++) {
            float a[8], bb[4];
            *(float4*)&a[0] = *(const float4*)&As[kk][tm * 8];
            *(float4*)&a[4] = *(const float4*)&As[kk][tm * 8 + 4];
            *(float4*)&bb[0] = *(const float4*)&Bs[kk][tn * 4];
#pragma unroll
            for (int i = 0; i < 8; i++)
#pragma unroll
                for (int j = 0; j < 4; j++)
                    acc[i][j] += a[i] * bb[j];
        }
        __syncthreads();
    }

    int mbase = m0 + tm * 8;
#pragma unroll
    for (int i = 0; i < 8; i++) {
        int m = mbase + i;
        int n = m >> 12, mp = m & 4095;
        float* op = out + ((size_t)n * OC) * 4096 + mp;
#pragma unroll
        for (int j = 0; j < 4; j++)
            op[(size_t)(o0 + tn * 4 + j) * 4096] = acc[i][j];
    }
}

// ---------------------------------------------------------------------------
extern "C" void kernel_launch(void* const* d_in, const int* in_sizes, int n_in,
                              void* d_out, int out_size)
{
    const float* x      = (const float*)d_in[0];
    const float* conv_w = (const float*)d_in[1];
    const float* conv_b = (const float*)d_in[2];
    const float* dcn_w  = (const float*)d_in[3];
    float* out = (float*)d_out;

    conv_offset_kernel<<<dim3(64, 4), 256>>>(x, conv_w, conv_b);
    permute_w_kernel<<<KDIM, 256>>>(dcn_w);
    sample_kernel<<<dim3(64, 4), 256>>>(x);
    sgemm_kernel<<<dim3(MDIM / 128, OC / 64), 256>>>(out);
}

// round 4
// speedup vs baseline: 1.0124x; 1.0124x over previous
#include <cuda_runtime.h>
#include <cuda_bf16.h>
#include <math.h>

// Shapes (fixed for this problem)
//   x:            (4, 256, 64, 64)  fp32
//   conv_offset_w:(27, 256, 3, 3)   fp32
//   conv_offset_b:(27,)             fp32
//   dcn_weight:   (256, 256, 3, 3)  fp32
//   out:          (4, 256, 64, 64)  fp32
//
// Pipeline:
//   K1 conv_offset  -> g_om   [4][27][64][64]
//   K2 permute      -> g_wperm[k=kk*256+c][o]           (2304 x 256)
//   K3 sample       -> g_valT [k=kk*256+c][m=n*4096+p]  (2304 x 16384)
//   K4 sgemm        -> out[n][o][p] = sum_k valT[k][m] * wperm[k][o]

#define NN 4
#define CC 256
#define HH 64
#define WW 64
#define OC 256
#define KDIM 2304          // 9 * 256
#define MDIM 16384         // 4 * 64 * 64

__device__ float g_om[NN * 27 * HH * WW];            // 1.77 MB
__device__ float g_wperm[KDIM * OC];                 // 2.36 MB
__device__ float g_valT[(size_t)KDIM * MDIM];        // 151 MB

// ---------------------------------------------------------------------------
// K1: offset conv. grid (64 y, 4 n), 256 threads = 64 pixels x 4 channel-groups
// ---------------------------------------------------------------------------
__global__ __launch_bounds__(256) void conv_offset_kernel(
    const float* __restrict__ x, const float* __restrict__ w,
    const float* __restrict__ b)
{
    int y = blockIdx.x, n = blockIdx.y;
    int t = threadIdx.x;
    int p = t & 63, g = t >> 6;

    __shared__ __align__(16) float sm[6912];
    float* xs = sm;         // [4][3][66] = 792 (padded region to 800)
    float* ws = sm + 800;   // [4][27][12] = 1296

    float acc[27];
#pragma unroll
    for (int oc = 0; oc < 27; oc++) acc[oc] = 0.f;

    for (int i = 0; i < 64; i++) {
        // stage x rows y-1..y+1 for the 4 channels {i, 64+i, 128+i, 192+i}
        for (int idx = t; idx < 792; idx += 256) {
            int gg = idx / 198, rem = idx - gg * 198;
            int r = rem / 66, j = rem - r * 66;
            int yy = y + r - 1, xx = j - 1;
            float v = 0.f;
            if (yy >= 0 && yy < HH && xx >= 0 && xx < WW)
                v = x[(((size_t)(n * CC + gg * 64 + i) * HH) + yy) * WW + xx];
            xs[(gg * 3 + r) * 66 + j] = v;
        }
        // stage weights for those channels: [g][oc][12] (9 used, 12 for f4 align)
        for (int idx = t; idx < 972; idx += 256) {
            int gg = idx / 243, rem = idx - gg * 243;
            int oc = rem / 9, kq = rem - oc * 9;
            ws[(gg * 27 + oc) * 12 + kq] = w[(oc * CC + gg * 64 + i) * 9 + kq];
        }
        __syncthreads();

        float tv[9];
#pragma unroll
        for (int r = 0; r < 3; r++)
#pragma unroll
            for (int s = 0; s < 3; s++)
                tv[r * 3 + s] = xs[(g * 3 + r) * 66 + p + s];

        const float4* wsg = (const float4*)(ws + g * 27 * 12);
#pragma unroll
        for (int oc = 0; oc < 27; oc++) {
            float4 w0 = wsg[oc * 3 + 0];
            float4 w1 = wsg[oc * 3 + 1];
            float  w8 = ws[(g * 27 + oc) * 12 + 8];
            acc[oc] += tv[0] * w0.x + tv[1] * w0.y + tv[2] * w0.z + tv[3] * w0.w
                     + tv[4] * w1.x + tv[5] * w1.y + tv[6] * w1.z + tv[7] * w1.w
                     + tv[8] * w8;
        }
        __syncthreads();
    }

    // cross-group reduction through smem (aliases xs/ws, safe after sync)
    float* red = sm;  // [4*64][27] = 6912
#pragma unroll
    for (int oc = 0; oc < 27; oc++) red[(g * 64 + p) * 27 + oc] = acc[oc];
    __syncthreads();
    for (int idx = t; idx < 1728; idx += 256) {
        int p2 = idx / 27, oc = idx - p2 * 27;
        float s = red[p2 * 27 + oc] + red[(64 + p2) * 27 + oc]
                + red[(128 + p2) * 27 + oc] + red[(192 + p2) * 27 + oc] + b[oc];
        g_om[(((size_t)n * 27 + oc) * HH + y) * WW + p2] = s;
    }
}

// ---------------------------------------------------------------------------
// K2: permute dcn_weight (o,c,kk) -> wperm[k=kk*256+c][o]
// ---------------------------------------------------------------------------
__global__ __launch_bounds__(256) void permute_w_kernel(const float* __restrict__ dw)
{
    int t = blockIdx.x * 256 + threadIdx.x;   // t = k*256 + o
    int o = t & 255;
    int k = t >> 8;
    int c = k & 255;
    int kk = k >> 8;
    g_wperm[t] = dw[(o * CC + c) * 9 + kk];
}

// ---------------------------------------------------------------------------
// K3: deformable bilinear sampling -> g_valT[k][m]
// grid (64 y, 4 n), 256 threads = 64 pixels x 4 channel-groups
// ---------------------------------------------------------------------------
__global__ __launch_bounds__(256) void sample_kernel(const float* __restrict__ x)
{
    int y = blockIdx.x, n = blockIdx.y;
    int t = threadIdx.x;

    __shared__ __align__(16) int   soff[576][4];
    __shared__ __align__(16) float swt[576][4];

    // Phase A: per (pixel, kk) tap metadata: 4 clamped tap offsets + 4
    // mask-folded bilinear weights (0 for out-of-image taps).
    for (int idx = t; idx < 576; idx += 256) {
        int p = idx / 9, kk = idx - p * 9;
        const float* omn = g_om + (size_t)n * 27 * 4096 + y * 64 + p;
        float oy = omn[(size_t)(2 * kk) * 4096];
        float ox = omn[(size_t)(2 * kk + 1) * 4096];
        float mv = omn[(size_t)(18 + kk) * 4096];
        float m  = 1.f / (1.f + __expf(-mv));

        float py = (float)(y + kk / 3) + oy;          // base(y+1) + inner(ky-1)
        float px = (float)(p + (kk % 3)) + ox;        // base(p+1) + inner(kx-1)
        py = fminf(fmaxf(py, 0.f), 65.f);
        px = fminf(fmaxf(px, 0.f), 65.f);
        float fy = floorf(py), fx = floorf(px);
        int y1 = (int)fy, x1 = (int)fx;
        float ly = py - fy, lx = px - fx;
        float hy = 1.f - ly, hx = 1.f - lx;
        float wt0 = hy * hx, wt1 = hy * lx, wt2 = ly * hx, wt3 = ly * lx;

#pragma unroll
        for (int q = 0; q < 4; q++) {
            int Y = y1 + (q >> 1);
            int X = x1 + (q & 1);
            bool valid = (Y >= 1 && Y <= 64 && X >= 1 && X <= 64);
            int Yc = min(max(Y, 1), 64), Xc = min(max(X, 1), 64);
            float wq = (q == 0) ? wt0 : (q == 1) ? wt1 : (q == 2) ? wt2 : wt3;
            soff[idx][q] = (Yc - 1) * 64 + (Xc - 1);
            swt[idx][q]  = valid ? wq * m : 0.f;
        }
    }
    __syncthreads();

    // Phase B: lanes over pixels (coalesced loads AND stores); metadata hoisted
    // to registers (channel-independent).
    int p = t & 63, g = t >> 6;
    int   ro[36];
    float rw[36];
#pragma unroll
    for (int kk = 0; kk < 9; kk++) {
        int4   o4 = *(const int4*)  &soff[p * 9 + kk][0];
        float4 w4 = *(const float4*)&swt [p * 9 + kk][0];
        ro[kk * 4 + 0] = o4.x; ro[kk * 4 + 1] = o4.y;
        ro[kk * 4 + 2] = o4.z; ro[kk * 4 + 3] = o4.w;
        rw[kk * 4 + 0] = w4.x; rw[kk * 4 + 1] = w4.y;
        rw[kk * 4 + 2] = w4.z; rw[kk * 4 + 3] = w4.w;
    }

    size_t mbase = (size_t)n * 4096 + (size_t)y * 64 + p;
    for (int j = 0; j < 64; j++) {
        int c = g * 64 + j;
        const float* xb = x + ((size_t)(n * CC + c)) * 4096;
        float* vb = g_valT + (size_t)c * MDIM + mbase;
#pragma unroll
        for (int kk = 0; kk < 9; kk++) {
            float v = rw[kk * 4 + 0] * __ldg(&xb[ro[kk * 4 + 0]])
                    + rw[kk * 4 + 1] * __ldg(&xb[ro[kk * 4 + 1]])
                    + rw[kk * 4 + 2] * __ldg(&xb[ro[kk * 4 + 2]])
                    + rw[kk * 4 + 3] * __ldg(&xb[ro[kk * 4 + 3]]);
            vb[(size_t)kk * 256 * MDIM] = v;
        }
    }
}

// ---------------------------------------------------------------------------
// K4: SGEMM  C[m][o] = sum_k valT[k][m] * wperm[k][o]
// BM=128, BN=64, BK=16, 256 threads, 8x4 micro-tile
// ---------------------------------------------------------------------------
__global__ __launch_bounds__(256) void sgemm_kernel(float* __restrict__ out)
{
    __shared__ __align__(16) float As[16][128];
    __shared__ __align__(16) float Bs[16][64];

    int t = threadIdx.x;
    int m0 = blockIdx.x * 128, o0 = blockIdx.y * 64;
    int tm = t >> 4, tn = t & 15;

    float acc[8][4];
#pragma unroll
    for (int i = 0; i < 8; i++)
#pragma unroll
        for (int j = 0; j < 4; j++) acc[i][j] = 0.f;

    int ar0 = t >> 5;            // rows 0..7
    int ac  = (t & 31) * 4;
    int ar1 = ar0 + 8;           // rows 8..15
    int br  = t >> 4;            // 0..15
    int bc  = (t & 15) * 4;

    for (int k0 = 0; k0 < KDIM; k0 += 16) {
        *(float4*)&As[ar0][ac] = *(const float4*)&g_valT[(size_t)(k0 + ar0) * MDIM + m0 + ac];
        *(float4*)&As[ar1][ac] = *(const float4*)&g_valT[(size_t)(k0 + ar1) * MDIM + m0 + ac];
        *(float4*)&Bs[br][bc]  = *(const float4*)&g_wperm[(size_t)(k0 + br) * OC + o0 + bc];
        __syncthreads();
#pragma unroll
        for (int kk = 0; kk < 16; kk++) {
            float a[8], bb[4];
            *(float4*)&a[0] = *(const float4*)&As[kk][tm * 8];
            *(float4*)&a[4] = *(const float4*)&As[kk][tm * 8 + 4];
            *(float4*)&bb[0] = *(const float4*)&Bs[kk][tn * 4];
#pragma unroll
            for (int i = 0; i < 8; i++)
#pragma unroll
                for (int j = 0; j < 4; j++)
                    acc[i][j] += a[i] * bb[j];
        }
        __syncthreads();
    }

    int mbase = m0 + tm * 8;
#pragma unroll
    for (int i = 0; i < 8; i++) {
        int m = mbase + i;
        int n = m >> 12, mp = m & 4095;
        float* op = out + ((size_t)n * OC) * 4096 + mp;
#pragma unroll
        for (int j = 0; j < 4; j++)
            op[(size_t)(o0 + tn * 4 + j) * 4096] = acc[i][j];
    }
}

// ---------------------------------------------------------------------------
extern "C" void kernel_launch(void* const* d_in, const int* in_sizes, int n_in,
                              void* d_out, int out_size)
{
    const float* x      = (const float*)d_in[0];
    const float* conv_w = (const float*)d_in[1];
    const float* conv_b = (const float*)d_in[2];
    const float* dcn_w  = (const float*)d_in[3];
    float* out = (float*)d_out;

    conv_offset_kernel<<<dim3(64, 4), 256>>>(x, conv_w, conv_b);
    permute_w_kernel<<<KDIM, 256>>>(dcn_w);
    sample_kernel<<<dim3(64, 4), 256>>>(x);
    sgemm_kernel<<<dim3(MDIM / 128, OC / 64), 256>>>(out);
}

// round 6
// speedup vs baseline: 1.8614x; 1.8385x over previous
#include <cuda_runtime.h>
#include <cuda_bf16.h>
#include <math.h>
#include <cstdint>

// Shapes (fixed)
//   x: (4,256,64,64) f32 | conv_offset_w: (27,256,3,3) | conv_offset_b: (27,)
//   dcn_weight: (256,256,3,3) | out: (4,256,64,64) f32
//
// Pipeline:
//   K1 conv_offset -> g_om[4][27][64][64]
//   K2 permute     -> g_wB [o][k']  (256 x 2304), tf32-rounded, k 8-group permuted
//   K3 sample      -> g_val[m][k']  (16384 x 2304), tf32-rounded, same permutation
//   K4 mma.sync tf32 GEMM: out[m][o] = sum_k g_val[m][k] * g_wB[o][k]
//
// k-permutation (within each 8-group): pos(w) = ((w&3)<<1)|(w>>2). This makes
// the mma.m16n8k8 per-thread fragment pair (col c, col c+4) CONTIGUOUS in
// memory, so all smem fragment loads are ld.shared.v2.b32.

#define NN 4
#define CC 256
#define HH 64
#define WW 64
#define OC 256
#define KDIM 2304
#define MDIM 16384

__device__ __align__(128) float g_om[NN * 27 * HH * WW];
__device__ __align__(128) float g_wB[OC * KDIM];
__device__ __align__(128) float g_val[(size_t)MDIM * KDIM];

__device__ __forceinline__ float to_tf32(float v) {
    uint32_t u;
    asm("cvt.rna.tf32.f32 %0, %1;" : "=r"(u) : "f"(v));
    return __uint_as_float(u);
}

__device__ __forceinline__ uint32_t smem_u32(const void* p) {
    uint32_t a;
    asm("{ .reg .u64 t; cvta.to.shared.u64 t, %1; cvt.u32.u64 %0, t; }"
        : "=r"(a) : "l"(p));
    return a;
}

__device__ __forceinline__ void cp_async16(uint32_t d, const void* s) {
    asm volatile("cp.async.cg.shared.global [%0], [%1], 16;"
                 :: "r"(d), "l"(s) : "memory");
}

// ---------------------------------------------------------------------------
// K1: offset conv (unchanged from R1 — known correct)
// ---------------------------------------------------------------------------
__global__ __launch_bounds__(256) void conv_offset_kernel(
    const float* __restrict__ x, const float* __restrict__ w,
    const float* __restrict__ b)
{
    int y = blockIdx.x, n = blockIdx.y;
    int t = threadIdx.x;
    int p = t & 63, g = t >> 6;

    __shared__ __align__(16) float sm[6912];
    float* xs = sm;
    float* ws = sm + 800;

    float acc[27];
#pragma unroll
    for (int oc = 0; oc < 27; oc++) acc[oc] = 0.f;

    for (int i = 0; i < 64; i++) {
        for (int idx = t; idx < 792; idx += 256) {
            int gg = idx / 198, rem = idx - gg * 198;
            int r = rem / 66, j = rem - r * 66;
            int yy = y + r - 1, xx = j - 1;
            float v = 0.f;
            if (yy >= 0 && yy < HH && xx >= 0 && xx < WW)
                v = x[(((size_t)(n * CC + gg * 64 + i) * HH) + yy) * WW + xx];
            xs[(gg * 3 + r) * 66 + j] = v;
        }
        for (int idx = t; idx < 972; idx += 256) {
            int gg = idx / 243, rem = idx - gg * 243;
            int oc = rem / 9, kq = rem - oc * 9;
            ws[(gg * 27 + oc) * 12 + kq] = w[(oc * CC + gg * 64 + i) * 9 + kq];
        }
        __syncthreads();

        float tv[9];
#pragma unroll
        for (int r = 0; r < 3; r++)
#pragma unroll
            for (int s = 0; s < 3; s++)
                tv[r * 3 + s] = xs[(g * 3 + r) * 66 + p + s];

        const float4* wsg = (const float4*)(ws + g * 27 * 12);
#pragma unroll
        for (int oc = 0; oc < 27; oc++) {
            float4 w0 = wsg[oc * 3 + 0];
            float4 w1 = wsg[oc * 3 + 1];
            float  w8 = ws[(g * 27 + oc) * 12 + 8];
            acc[oc] += tv[0] * w0.x + tv[1] * w0.y + tv[2] * w0.z + tv[3] * w0.w
                     + tv[4] * w1.x + tv[5] * w1.y + tv[6] * w1.z + tv[7] * w1.w
                     + tv[8] * w8;
        }
        __syncthreads();
    }

    float* red = sm;
#pragma unroll
    for (int oc = 0; oc < 27; oc++) red[(g * 64 + p) * 27 + oc] = acc[oc];
    __syncthreads();
    for (int idx = t; idx < 1728; idx += 256) {
        int p2 = idx / 27, oc = idx - p2 * 27;
        float s = red[p2 * 27 + oc] + red[(64 + p2) * 27 + oc]
                + red[(128 + p2) * 27 + oc] + red[(192 + p2) * 27 + oc] + b[oc];
        g_om[(((size_t)n * 27 + oc) * HH + y) * WW + p2] = s;
    }
}

// ---------------------------------------------------------------------------
// K2: permute dcn_weight (o,c,kk) -> g_wB[o][k'], tf32-rounded, k-permuted
// ---------------------------------------------------------------------------
__global__ __launch_bounds__(256) void permute_w_kernel(const float* __restrict__ dw)
{
    int o = blockIdx.x;
    int c = threadIdx.x;
    int cp = (c & 0xF8) | ((c & 3) << 1) | ((c >> 2) & 1);
    const float* src = dw + (size_t)(o * CC + c) * 9;
    float* dst = g_wB + (size_t)o * KDIM + cp;
#pragma unroll
    for (int kk = 0; kk < 9; kk++)
        dst[kk * 256] = to_tf32(src[kk]);
}

// ---------------------------------------------------------------------------
// K3: deformable sampling -> g_val[m][k'] (K-major, k-permuted)
// grid (64 y, 4 n), 256 threads
// ---------------------------------------------------------------------------
__global__ __launch_bounds__(256) void sample_kernel(const float* __restrict__ x)
{
    int y = blockIdx.x, n = blockIdx.y;
    int t = threadIdx.x;

    __shared__ __align__(16) char sbuf[37440];
    int   (*soff)[4] = (int(*)[4])sbuf;            // [576][4]
    float (*swt)[4]  = (float(*)[4])(sbuf + 9216); // [576][4]
    float (*sv)[16][65] = (float(*)[16][65])sbuf;  // [9][16][65] (reuses sbuf)

    // Phase A: per (pixel, kk) tap metadata
    for (int idx = t; idx < 576; idx += 256) {
        int p = idx / 9, kk = idx - p * 9;
        const float* omn = g_om + (size_t)n * 27 * 4096 + y * 64 + p;
        float oy = omn[(size_t)(2 * kk) * 4096];
        float ox = omn[(size_t)(2 * kk + 1) * 4096];
        float mv = omn[(size_t)(18 + kk) * 4096];
        float m  = 1.f / (1.f + __expf(-mv));

        float py = (float)(y + kk / 3) + oy;
        float px = (float)(p + (kk % 3)) + ox;
        py = fminf(fmaxf(py, 0.f), 65.f);
        px = fminf(fmaxf(px, 0.f), 65.f);
        float fy = floorf(py), fx = floorf(px);
        int y1 = (int)fy, x1 = (int)fx;
        float ly = py - fy, lx = px - fx;
        float hy = 1.f - ly, hx = 1.f - lx;
        float wt0 = hy * hx, wt1 = hy * lx, wt2 = ly * hx, wt3 = ly * lx;

#pragma unroll
        for (int q = 0; q < 4; q++) {
            int Y = y1 + (q >> 1);
            int X = x1 + (q & 1);
            bool valid = (Y >= 1 && Y <= 64 && X >= 1 && X <= 64);
            int Yc = min(max(Y, 1), 64), Xc = min(max(X, 1), 64);
            float wq = (q == 0) ? wt0 : (q == 1) ? wt1 : (q == 2) ? wt2 : wt3;
            soff[idx][q] = (Yc - 1) * 64 + (Xc - 1);
            swt[idx][q]  = valid ? wq * m : 0.f;
        }
    }
    __syncthreads();

    // Hoist per-pixel metadata to registers (frees sbuf for sv reuse)
    int p = t & 63, q = t >> 6;
    int   ro[36];
    float rw[36];
#pragma unroll
    for (int kk = 0; kk < 9; kk++) {
        int4   o4 = *(const int4*)  &soff[p * 9 + kk][0];
        float4 w4 = *(const float4*)&swt [p * 9 + kk][0];
        ro[kk * 4 + 0] = o4.x; ro[kk * 4 + 1] = o4.y;
        ro[kk * 4 + 2] = o4.z; ro[kk * 4 + 3] = o4.w;
        rw[kk * 4 + 0] = w4.x; rw[kk * 4 + 1] = w4.y;
        rw[kk * 4 + 2] = w4.z; rw[kk * 4 + 3] = w4.w;
    }
    __syncthreads();

    size_t mbase = (size_t)n * 4096 + (size_t)y * 64;

    for (int G = 0; G < 16; G++) {
        int c0 = G * 16;
#pragma unroll
        for (int cc = 0; cc < 4; cc++) {
            int c = c0 + q * 4 + cc;
            const float* xb = x + ((size_t)(n * CC + c)) * 4096;
#pragma unroll
            for (int kk = 0; kk < 9; kk++) {
                float v = rw[kk * 4 + 0] * __ldg(&xb[ro[kk * 4 + 0]])
                        + rw[kk * 4 + 1] * __ldg(&xb[ro[kk * 4 + 1]])
                        + rw[kk * 4 + 2] * __ldg(&xb[ro[kk * 4 + 2]])
                        + rw[kk * 4 + 3] * __ldg(&xb[ro[kk * 4 + 3]]);
                sv[kk][q * 4 + cc][p] = to_tf32(v);
            }
        }
        __syncthreads();
        {
            int cl = t & 15;
            // k-permuted channel slot within the 16-group
            int clp = (cl & 8) | ((cl & 3) << 1) | ((cl >> 2) & 1);
            int pi = t >> 4;
            for (int it = 0; it < 36; it++) {
                int pp = pi / 9, kk = pi - pp * 9;
                g_val[(mbase + pp) * KDIM + kk * 256 + c0 + clp] = sv[kk][cl][pp];
                pi += 16;
            }
        }
        __syncthreads();
    }
}

// ---------------------------------------------------------------------------
// K4: tf32 mma.sync GEMM.  Block: BM=128 x BN=256, BK=32, 4-stage cp.async.
// 8 warps (2x4), warp tile 64x64 via m16n8k8 fragments.
// ---------------------------------------------------------------------------
#define NTILES 72
#define STAGE_BYTES 49152   // 16KB A + 32KB B

#define LOAD_STAGE(tt_) do {                                                  \
    uint32_t so_ = ((tt_) & 3) * STAGE_BYTES;                                 \
    size_t   ko_ = (size_t)(tt_) * 128;  /* BK=32 floats = 128B */            \
    _Pragma("unroll")                                                         \
    for (int i_ = 0; i_ < 4; i_++)                                            \
        cp_async16(dA0 + so_ + i_ * 4096,                                     \
                   gA0 + ko_ + (size_t)i_ * 32 * KDIM * 4);                   \
    _Pragma("unroll")                                                         \
    for (int i_ = 0; i_ < 8; i_++)                                            \
        cp_async16(dB0 + so_ + i_ * 4096,                                     \
                   gB0 + ko_ + (size_t)i_ * 32 * KDIM * 4);                   \
} while (0)

__global__ __launch_bounds__(256, 1) void gemm_kernel(float* __restrict__ out)
{
    extern __shared__ __align__(128) char smem[];
    const int tid = threadIdx.x;
    const int m0 = blockIdx.x * 128;

    // cp.async thread assignment: 16B chunks, 8 per row of BK=32 floats
    const int ldrow = tid >> 3;          // 0..31
    const int ldcol = tid & 7;           // chunk in row
    const int swz   = ldcol ^ (ldrow & 7);
    const char* gA0 = (const char*)(g_val + (size_t)(m0 + ldrow) * KDIM) + ldcol * 16;
    const char* gB0 = (const char*)(g_wB  + (size_t)ldrow        * KDIM) + ldcol * 16;
    const uint32_t sbase = smem_u32(smem);
    const uint32_t dA0 = sbase + ldrow * 128 + swz * 16;
    const uint32_t dB0 = sbase + 16384 + ldrow * 128 + swz * 16;

    const int lane = tid & 31, warp = tid >> 5;
    const int g  = lane >> 2, tg = lane & 3;
    const int wm = (warp >> 2) * 64;     // warp m-origin (0 or 64)
    const int wn = (warp & 3) * 64;      // warp n-origin (0..192)

    float c[4][8][4];
#pragma unroll
    for (int i = 0; i < 4; i++)
#pragma unroll
        for (int j = 0; j < 8; j++)
#pragma unroll
            for (int r = 0; r < 4; r++) c[i][j][r] = 0.f;

    LOAD_STAGE(0); asm volatile("cp.async.commit_group;" ::: "memory");
    LOAD_STAGE(1); asm volatile("cp.async.commit_group;" ::: "memory");
    LOAD_STAGE(2); asm volatile("cp.async.commit_group;" ::: "memory");

    for (int t = 0; t < NTILES; t++) {
        asm volatile("cp.async.wait_group 2;" ::: "memory");
        __syncthreads();
        if (t + 3 < NTILES) LOAD_STAGE(t + 3);
        asm volatile("cp.async.commit_group;" ::: "memory");

        const uint32_t As = sbase + (t & 3) * STAGE_BYTES;
        const uint32_t Bs = As + 16384;

#pragma unroll
        for (int ks = 0; ks < 4; ks++) {
            const int ch = ks * 2 + (tg >> 1);
            const int hb = (tg & 1) << 3;

            uint32_t a[4][4];
#pragma unroll
            for (int mt = 0; mt < 4; mt++) {
                int r1 = wm + mt * 16 + g;
                int r2 = r1 + 8;
                uint32_t ad1 = As + r1 * 128 + ((ch ^ (r1 & 7)) << 4) + hb;
                uint32_t ad2 = As + r2 * 128 + ((ch ^ (r2 & 7)) << 4) + hb;
                asm volatile("ld.shared.v2.b32 {%0,%1}, [%2];"
                             : "=r"(a[mt][0]), "=r"(a[mt][2]) : "r"(ad1));
                asm volatile("ld.shared.v2.b32 {%0,%1}, [%2];"
                             : "=r"(a[mt][1]), "=r"(a[mt][3]) : "r"(ad2));
            }
            uint32_t b[8][2];
#pragma unroll
            for (int nt = 0; nt < 8; nt++) {
                int ro = wn + nt * 8 + g;
                uint32_t bd = Bs + ro * 128 + ((ch ^ (ro & 7)) << 4) + hb;
                asm volatile("ld.shared.v2.b32 {%0,%1}, [%2];"
                             : "=r"(b[nt][0]), "=r"(b[nt][1]) : "r"(bd));
            }
#pragma unroll
            for (int mt = 0; mt < 4; mt++)
#pragma unroll
                for (int nt = 0; nt < 8; nt++)
                    asm volatile(
                        "mma.sync.aligned.m16n8k8.row.col.f32.tf32.tf32.f32 "
                        "{%0,%1,%2,%3}, {%4,%5,%6,%7}, {%8,%9}, {%0,%1,%2,%3};"
                        : "+f"(c[mt][nt][0]), "+f"(c[mt][nt][1]),
                          "+f"(c[mt][nt][2]), "+f"(c[mt][nt][3])
                        : "r"(a[mt][0]), "r"(a[mt][1]), "r"(a[mt][2]), "r"(a[mt][3]),
                          "r"(b[nt][0]), "r"(b[nt][1]));
        }
    }

    // Epilogue: c[mt][nt] covers (m = wm+mt*16+{g,g+8}, o = wn+nt*8+{2tg,2tg+1})
    const int nimg = m0 >> 12;
    float* ob = out + (size_t)nimg * OC * 4096 + (m0 & 4095);
#pragma unroll
    for (int mt = 0; mt < 4; mt++) {
        int lm = wm + mt * 16 + g;
#pragma unroll
        for (int nt = 0; nt < 8; nt++) {
            int o = wn + nt * 8 + tg * 2;
            ob[(size_t)o * 4096 + lm]           = c[mt][nt][0];
            ob[(size_t)(o + 1) * 4096 + lm]     = c[mt][nt][1];
            ob[(size_t)o * 4096 + lm + 8]       = c[mt][nt][2];
            ob[(size_t)(o + 1) * 4096 + lm + 8] = c[mt][nt][3];
        }
    }
}

// ---------------------------------------------------------------------------
extern "C" void kernel_launch(void* const* d_in, const int* in_sizes, int n_in,
                              void* d_out, int out_size)
{
    const float* x      = (const float*)d_in[0];
    const float* conv_w = (const float*)d_in[1];
    const float* conv_b = (const float*)d_in[2];
    const float* dcn_w  = (const float*)d_in[3];
    float* out = (float*)d_out;

    const int gemm_smem = 4 * STAGE_BYTES;  // 192 KB
    cudaFuncSetAttribute(gemm_kernel, cudaFuncAttributeMaxDynamicSharedMemorySize,
                         gemm_smem);

    conv_offset_kernel<<<dim3(64, 4), 256>>>(x, conv_w, conv_b);
    permute_w_kernel<<<OC, 256>>>(dcn_w);
    sample_kernel<<<dim3(64, 4), 256>>>(x);
    gemm_kernel<<<MDIM / 128, 256, gemm_smem>>>(out);
}

// round 7
// speedup vs baseline: 2.0784x; 1.1165x over previous
#include <cuda_runtime.h>
#include <cuda_bf16.h>
#include <math.h>
#include <cstdint>

// Shapes (fixed)
//   x: (4,256,64,64) f32 | conv_offset_w: (27,256,3,3) | conv_offset_b: (27,)
//   dcn_weight: (256,256,3,3) | out: (4,256,64,64) f32
//
// Pipeline:
//   K1 conv_offset -> g_om[4][27][64][64]
//   K2 permute     -> g_wB[o][k'] (256 x 2304), tf32-rounded, k 8-group permuted
//   K3 FUSED sample+GEMM: per K-tile, gather the deformable-bilinear A tile
//      directly from x into smem (no g_val round-trip), then tf32 mma.sync.
//
// k-permutation within each 8-group: pos(w) = ((w&3)<<1)|(w>>2) — makes the
// m16n8k8 fragment column pair (c, c+4) contiguous -> ld.shared.v2 everywhere.

#define NN 4
#define CC 256
#define HH 64
#define WW 64
#define OC 256
#define KDIM 2304
#define MDIM 16384
#define NTILES 72

__device__ __align__(128) float g_om[NN * 27 * HH * WW];
__device__ __align__(128) float g_wB[OC * KDIM];

__device__ __forceinline__ float to_tf32(float v) {
    uint32_t u;
    asm("cvt.rna.tf32.f32 %0, %1;" : "=r"(u) : "f"(v));
    return __uint_as_float(u);
}
__device__ __forceinline__ uint32_t smem_u32(const void* p) {
    uint32_t a;
    asm("{ .reg .u64 t; cvta.to.shared.u64 t, %1; cvt.u32.u64 %0, t; }"
        : "=r"(a) : "l"(p));
    return a;
}
__device__ __forceinline__ void cp_async16(uint32_t d, const void* s) {
    asm volatile("cp.async.cg.shared.global [%0], [%1], 16;"
                 :: "r"(d), "l"(s) : "memory");
}

// ---------------------------------------------------------------------------
// K1: offset conv (unchanged — known correct)
// ---------------------------------------------------------------------------
__global__ __launch_bounds__(256) void conv_offset_kernel(
    const float* __restrict__ x, const float* __restrict__ w,
    const float* __restrict__ b)
{
    int y = blockIdx.x, n = blockIdx.y;
    int t = threadIdx.x;
    int p = t & 63, g = t >> 6;

    __shared__ __align__(16) float sm[6912];
    float* xs = sm;
    float* ws = sm + 800;

    float acc[27];
#pragma unroll
    for (int oc = 0; oc < 27; oc++) acc[oc] = 0.f;

    for (int i = 0; i < 64; i++) {
        for (int idx = t; idx < 792; idx += 256) {
            int gg = idx / 198, rem = idx - gg * 198;
            int r = rem / 66, j = rem - r * 66;
            int yy = y + r - 1, xx = j - 1;
            float v = 0.f;
            if (yy >= 0 && yy < HH && xx >= 0 && xx < WW)
                v = x[(((size_t)(n * CC + gg * 64 + i) * HH) + yy) * WW + xx];
            xs[(gg * 3 + r) * 66 + j] = v;
        }
        for (int idx = t; idx < 972; idx += 256) {
            int gg = idx / 243, rem = idx - gg * 243;
            int oc = rem / 9, kq = rem - oc * 9;
            ws[(gg * 27 + oc) * 12 + kq] = w[(oc * CC + gg * 64 + i) * 9 + kq];
        }
        __syncthreads();

        float tv[9];
#pragma unroll
        for (int r = 0; r < 3; r++)
#pragma unroll
            for (int s = 0; s < 3; s++)
                tv[r * 3 + s] = xs[(g * 3 + r) * 66 + p + s];

        const float4* wsg = (const float4*)(ws + g * 27 * 12);
#pragma unroll
        for (int oc = 0; oc < 27; oc++) {
            float4 w0 = wsg[oc * 3 + 0];
            float4 w1 = wsg[oc * 3 + 1];
            float  w8 = ws[(g * 27 + oc) * 12 + 8];
            acc[oc] += tv[0] * w0.x + tv[1] * w0.y + tv[2] * w0.z + tv[3] * w0.w
                     + tv[4] * w1.x + tv[5] * w1.y + tv[6] * w1.z + tv[7] * w1.w
                     + tv[8] * w8;
        }
        __syncthreads();
    }

    float* red = sm;
#pragma unroll
    for (int oc = 0; oc < 27; oc++) red[(g * 64 + p) * 27 + oc] = acc[oc];
    __syncthreads();
    for (int idx = t; idx < 1728; idx += 256) {
        int p2 = idx / 27, oc = idx - p2 * 27;
        float s = red[p2 * 27 + oc] + red[(64 + p2) * 27 + oc]
                + red[(128 + p2) * 27 + oc] + red[(192 + p2) * 27 + oc] + b[oc];
        g_om[(((size_t)n * 27 + oc) * HH + y) * WW + p2] = s;
    }
}

// ---------------------------------------------------------------------------
// K2: permute dcn_weight (o,c,kk) -> g_wB[o][k'], tf32-rounded, k-permuted
// ---------------------------------------------------------------------------
__global__ __launch_bounds__(256) void permute_w_kernel(const float* __restrict__ dw)
{
    int o = blockIdx.x;
    int c = threadIdx.x;
    int cp = (c & 0xF8) | ((c & 3) << 1) | ((c >> 2) & 1);
    const float* src = dw + (size_t)(o * CC + c) * 9;
    float* dst = g_wB + (size_t)o * KDIM + cp;
#pragma unroll
    for (int kk = 0; kk < 9; kk++)
        dst[kk * 256] = to_tf32(src[kk]);
}

// ---------------------------------------------------------------------------
// K3: FUSED deformable-sample + tf32 GEMM.
// BM=128 (one n-image, 2 y-rows), BN=256 (all o), BK=32 (one kk, 32 c).
// smem: A dbl-buf 2x16KB @0 | B 4-stage 4x32KB @32768 | metadata @163840
// ---------------------------------------------------------------------------
#define SM_A    0
#define SM_B    32768
#define SM_MOFF 163840
#define SM_MWT  182272
#define FUSED_SMEM 200704

__global__ __launch_bounds__(256, 1) void fused_gemm_kernel(
    const float* __restrict__ x, float* __restrict__ out)
{
    extern __shared__ __align__(128) char smem[];
    const uint32_t sbase = smem_u32(smem);
    const int tid = threadIdx.x;
    const int m0 = blockIdx.x * 128;
    const int nimg = m0 >> 12;
    const int y0 = (m0 & 4095) >> 6;          // covers rows y0, y0+1

    int4*   moff = (int4*)(smem + SM_MOFF);   // [128*9]
    float4* mwt  = (float4*)(smem + SM_MWT);  // [128*9]

    // ---- B cp.async assignment (16B chunks, identical layout to R6) ----
    const int ldrow = tid >> 3;               // 0..31
    const int ldcol = tid & 7;
    const int swzb  = ldcol ^ (ldrow & 7);
    const char* gB0 = (const char*)(g_wB + (size_t)ldrow * KDIM) + ldcol * 16;
    const uint32_t dB0 = sbase + SM_B + ldrow * 128 + swzb * 16;

#define LOAD_B(tt_) do {                                                      \
    uint32_t so_ = ((tt_) & 3) * 32768;                                       \
    size_t   ko_ = (size_t)(tt_) * 128;                                       \
    _Pragma("unroll")                                                         \
    for (int i_ = 0; i_ < 8; i_++)                                            \
        cp_async16(dB0 + so_ + i_ * 4096,                                     \
                   gB0 + ko_ + (size_t)i_ * 32 * KDIM * 4);                   \
} while (0)

    // Prologue: B stages 0..2 in flight while we compute metadata
    LOAD_B(0); asm volatile("cp.async.commit_group;" ::: "memory");
    LOAD_B(1); asm volatile("cp.async.commit_group;" ::: "memory");
    LOAD_B(2); asm volatile("cp.async.commit_group;" ::: "memory");

    // ---- metadata: per (pixel, kk): 4 clamped tap offsets + 4 folded wts ----
    for (int idx = tid; idx < 1152; idx += 256) {
        int p128 = idx / 9, kk = idx - p128 * 9;
        int yy = y0 + (p128 >> 6);
        int xx = p128 & 63;
        const float* omn = g_om + (size_t)nimg * 27 * 4096 + yy * 64 + xx;
        float oy = omn[(size_t)(2 * kk) * 4096];
        float ox = omn[(size_t)(2 * kk + 1) * 4096];
        float mv = omn[(size_t)(18 + kk) * 4096];
        float m  = 1.f / (1.f + __expf(-mv));

        float py = (float)(yy + kk / 3) + oy;
        float px = (float)(xx + (kk % 3)) + ox;
        py = fminf(fmaxf(py, 0.f), 65.f);
        px = fminf(fmaxf(px, 0.f), 65.f);
        float fy = floorf(py), fx = floorf(px);
        int y1 = (int)fy, x1 = (int)fx;
        float ly = py - fy, lx = px - fx;
        float hy = 1.f - ly, hx = 1.f - lx;
        float wq[4] = { hy * hx, hy * lx, ly * hx, ly * lx };

        int4 o4; float4 w4;
        int   ov[4]; float wv[4];
#pragma unroll
        for (int q = 0; q < 4; q++) {
            int Y = y1 + (q >> 1);
            int X = x1 + (q & 1);
            bool valid = (Y >= 1 && Y <= 64 && X >= 1 && X <= 64);
            int Yc = min(max(Y, 1), 64), Xc = min(max(X, 1), 64);
            ov[q] = (Yc - 1) * 64 + (Xc - 1);
            wv[q] = valid ? wq[q] * m : 0.f;
        }
        o4.x = ov[0]; o4.y = ov[1]; o4.z = ov[2]; o4.w = ov[3];
        w4.x = wv[0]; w4.y = wv[1]; w4.z = wv[2]; w4.w = wv[3];
        moff[idx] = o4;
        mwt[idx]  = w4;
    }
    __syncthreads();

    // ---- per-thread roles ----
    const int mloc = tid & 127;               // gather row (pixel)
    const int half = tid >> 7;                // 0: c 0..15, 1: c 16..31
    const int lane = tid & 31, warp = tid >> 5;
    const int g  = lane >> 2, tg = lane & 3;
    const int wm = (warp >> 2) * 64;
    const int wn = (warp & 3) * 64;

    const float* xn = x + (size_t)nimg * CC * 4096;

    float c[4][8][4];
#pragma unroll
    for (int i = 0; i < 4; i++)
#pragma unroll
        for (int j = 0; j < 8; j++)
#pragma unroll
            for (int r = 0; r < 4; r++) c[i][j][r] = 0.f;

    int   ro[4];
    float rw[4];

    for (int t = 0; t < NTILES; t++) {
        // reload tap metadata when kk changes (every 8 tiles)
        if ((t & 7) == 0) {
            int kk = t >> 3;
            int4   o4 = moff[mloc * 9 + kk];
            float4 w4 = mwt [mloc * 9 + kk];
            ro[0] = o4.x; ro[1] = o4.y; ro[2] = o4.z; ro[3] = o4.w;
            rw[0] = w4.x; rw[1] = w4.y; rw[2] = w4.z; rw[3] = w4.w;
        }

        // ---- gather A(t) into buffer t&1 (tf32, k-permuted, swizzled) ----
        {
            const int c0 = (t & 7) * 32;
            const float* xp = xn + (size_t)c0 * 4096;
            const uint32_t Aw = sbase + SM_A + (t & 1) * 16384 + mloc * 128;
#pragma unroll
            for (int p8 = 0; p8 < 2; p8++) {
#pragma unroll
                for (int q = 0; q < 4; q++) {
                    int ct = half * 16 + p8 * 8 + q;
                    const float* plo = xp + (size_t)ct * 4096;
                    const float* phi = plo + 4 * 4096;
                    float vlo = rw[0] * __ldg(&plo[ro[0]])
                              + rw[1] * __ldg(&plo[ro[1]])
                              + rw[2] * __ldg(&plo[ro[2]])
                              + rw[3] * __ldg(&plo[ro[3]]);
                    float vhi = rw[0] * __ldg(&phi[ro[0]])
                              + rw[1] * __ldg(&phi[ro[1]])
                              + rw[2] * __ldg(&phi[ro[2]])
                              + rw[3] * __ldg(&phi[ro[3]]);
                    int cp = (ct & 0x18) | (q << 1);      // even; pair = cp, cp+1
                    uint32_t chunk = cp >> 2;
                    uint32_t addr = Aw + ((chunk ^ (mloc & 7)) << 4)
                                  + ((cp & 3) << 2);
                    uint32_t rlo = __float_as_uint(to_tf32(vlo));
                    uint32_t rhi = __float_as_uint(to_tf32(vhi));
                    asm volatile("st.shared.v2.b32 [%0], {%1,%2};"
                                 :: "r"(addr), "r"(rlo), "r"(rhi) : "memory");
                }
            }
        }

        asm volatile("cp.async.wait_group 2;" ::: "memory");
        __syncthreads();   // A(t) STS drained + B(t) resident, block-visible

        if (t + 3 < NTILES) LOAD_B(t + 3);
        asm volatile("cp.async.commit_group;" ::: "memory");

        const uint32_t As = sbase + SM_A + (t & 1) * 16384;
        const uint32_t Bs = sbase + SM_B + (t & 3) * 32768;

#pragma unroll
        for (int ks = 0; ks < 4; ks++) {
            const int ch = ks * 2 + (tg >> 1);
            const int hb = (tg & 1) << 3;

            uint32_t a[4][4];
#pragma unroll
            for (int mt = 0; mt < 4; mt++) {
                int r1 = wm + mt * 16 + g;
                int r2 = r1 + 8;
                uint32_t ad1 = As + r1 * 128 + ((ch ^ (r1 & 7)) << 4) + hb;
                uint32_t ad2 = As + r2 * 128 + ((ch ^ (r2 & 7)) << 4) + hb;
                asm volatile("ld.shared.v2.b32 {%0,%1}, [%2];"
                             : "=r"(a[mt][0]), "=r"(a[mt][2]) : "r"(ad1));
                asm volatile("ld.shared.v2.b32 {%0,%1}, [%2];"
                             : "=r"(a[mt][1]), "=r"(a[mt][3]) : "r"(ad2));
            }
            uint32_t b[8][2];
#pragma unroll
            for (int nt = 0; nt < 8; nt++) {
                int rr = wn + nt * 8 + g;
                uint32_t bd = Bs + rr * 128 + ((ch ^ (rr & 7)) << 4) + hb;
                asm volatile("ld.shared.v2.b32 {%0,%1}, [%2];"
                             : "=r"(b[nt][0]), "=r"(b[nt][1]) : "r"(bd));
            }
#pragma unroll
            for (int mt = 0; mt < 4; mt++)
#pragma unroll
                for (int nt = 0; nt < 8; nt++)
                    asm volatile(
                        "mma.sync.aligned.m16n8k8.row.col.f32.tf32.tf32.f32 "
                        "{%0,%1,%2,%3}, {%4,%5,%6,%7}, {%8,%9}, {%0,%1,%2,%3};"
                        : "+f"(c[mt][nt][0]), "+f"(c[mt][nt][1]),
                          "+f"(c[mt][nt][2]), "+f"(c[mt][nt][3])
                        : "r"(a[mt][0]), "r"(a[mt][1]), "r"(a[mt][2]), "r"(a[mt][3]),
                          "r"(b[nt][0]), "r"(b[nt][1]));
        }
    }

    // ---- epilogue (unchanged) ----
    float* ob = out + (size_t)nimg * OC * 4096 + (m0 & 4095);
#pragma unroll
    for (int mt = 0; mt < 4; mt++) {
        int lm = wm + mt * 16 + g;
#pragma unroll
        for (int nt = 0; nt < 8; nt++) {
            int o = wn + nt * 8 + tg * 2;
            ob[(size_t)o * 4096 + lm]           = c[mt][nt][0];
            ob[(size_t)(o + 1) * 4096 + lm]     = c[mt][nt][1];
            ob[(size_t)o * 4096 + lm + 8]       = c[mt][nt][2];
            ob[(size_t)(o + 1) * 4096 + lm + 8] = c[mt][nt][3];
        }
    }
}

// ---------------------------------------------------------------------------
extern "C" void kernel_launch(void* const* d_in, const int* in_sizes, int n_in,
                              void* d_out, int out_size)
{
    const float* x      = (const float*)d_in[0];
    const float* conv_w = (const float*)d_in[1];
    const float* conv_b = (const float*)d_in[2];
    const float* dcn_w  = (const float*)d_in[3];
    float* out = (float*)d_out;

    cudaFuncSetAttribute(fused_gemm_kernel,
                         cudaFuncAttributeMaxDynamicSharedMemorySize, FUSED_SMEM);

    conv_offset_kernel<<<dim3(64, 4), 256>>>(x, conv_w, conv_b);
    permute_w_kernel<<<OC, 256>>>(dcn_w);
    fused_gemm_kernel<<<MDIM / 128, 256, FUSED_SMEM>>>(x, out);
}

// round 8
// speedup vs baseline: 2.6721x; 1.2857x over previous
#include <cuda_runtime.h>
#include <cuda_bf16.h>
#include <math.h>
#include <cstdint>

// Shapes (fixed)
//   x: (4,256,64,64) f32 | conv_offset_w: (27,256,3,3) | conv_offset_b: (27,)
//   dcn_weight: (256,256,3,3) | out: (4,256,64,64) f32
//
// Pipeline (all tensor-core now):
//   K2a permute dcn_weight   -> g_wB[o][k']  tf32, k 8-group permuted
//   K2b permute conv_offset_w-> g_wOffHi/Lo[32][k']  split-tf32, rows 27..31 = 0
//   K3  offset implicit GEMM -> g_om[4][27][64][64]  (split-tf32: hi*hi+hi*lo+lo*hi)
//   K4  FUSED deformable-sample + tf32 GEMM -> out
//
// k-permutation within each 8-group: pos(w) = ((w&3)<<1)|(w>>2) — makes the
// m16n8k8 fragment column pair (c, c+4) contiguous -> ld.shared.v2 everywhere.

#define NN 4
#define CC 256
#define HH 64
#define WW 64
#define OC 256
#define KDIM 2304
#define MDIM 16384
#define NTILES 72

__device__ __align__(128) float g_om[NN * 27 * HH * WW];
__device__ __align__(128) float g_wB[OC * KDIM];
__device__ __align__(128) float g_wOffHi[32 * KDIM];
__device__ __align__(128) float g_wOffLo[32 * KDIM];

__device__ __forceinline__ float to_tf32(float v) {
    uint32_t u;
    asm("cvt.rna.tf32.f32 %0, %1;" : "=r"(u) : "f"(v));
    return __uint_as_float(u);
}
__device__ __forceinline__ uint32_t smem_u32(const void* p) {
    uint32_t a;
    asm("{ .reg .u64 t; cvta.to.shared.u64 t, %1; cvt.u32.u64 %0, t; }"
        : "=r"(a) : "l"(p));
    return a;
}
__device__ __forceinline__ void cp_async16(uint32_t d, const void* s) {
    asm volatile("cp.async.cg.shared.global [%0], [%1], 16;"
                 :: "r"(d), "l"(s) : "memory");
}

#define MMA_TF32(c_, a_, b_)                                                  \
    asm volatile(                                                             \
        "mma.sync.aligned.m16n8k8.row.col.f32.tf32.tf32.f32 "                 \
        "{%0,%1,%2,%3}, {%4,%5,%6,%7}, {%8,%9}, {%0,%1,%2,%3};"               \
        : "+f"((c_)[0]), "+f"((c_)[1]), "+f"((c_)[2]), "+f"((c_)[3])          \
        : "r"((a_)[0]), "r"((a_)[1]), "r"((a_)[2]), "r"((a_)[3]),             \
          "r"((b_)[0]), "r"((b_)[1]))

// ---------------------------------------------------------------------------
// K2a: permute dcn_weight (o,c,kk) -> g_wB[o][k'], tf32-rounded, k-permuted
// ---------------------------------------------------------------------------
__global__ __launch_bounds__(256) void permute_w_kernel(const float* __restrict__ dw)
{
    int o = blockIdx.x;
    int c = threadIdx.x;
    int cp = (c & 0xF8) | ((c & 3) << 1) | ((c >> 2) & 1);
    const float* src = dw + (size_t)(o * CC + c) * 9;
    float* dst = g_wB + (size_t)o * KDIM + cp;
#pragma unroll
    for (int kk = 0; kk < 9; kk++)
        dst[kk * 256] = to_tf32(src[kk]);
}

// ---------------------------------------------------------------------------
// K2b: permute conv_offset_w (27,c,kk) -> g_wOffHi/Lo[32][k'] (split-tf32)
// ---------------------------------------------------------------------------
__global__ __launch_bounds__(256) void permute_woff_kernel(const float* __restrict__ wo)
{
    int o = blockIdx.x;      // 0..31
    int c = threadIdx.x;
    int cp = (c & 0xF8) | ((c & 3) << 1) | ((c >> 2) & 1);
    float* dh = g_wOffHi + (size_t)o * KDIM + cp;
    float* dl = g_wOffLo + (size_t)o * KDIM + cp;
    if (o < 27) {
        const float* src = wo + (size_t)(o * CC + c) * 9;
#pragma unroll
        for (int kk = 0; kk < 9; kk++) {
            float v = src[kk];
            float h = to_tf32(v);
            dh[kk * 256] = h;
            dl[kk * 256] = to_tf32(v - h);
        }
    } else {
#pragma unroll
        for (int kk = 0; kk < 9; kk++) { dh[kk * 256] = 0.f; dl[kk * 256] = 0.f; }
    }
}

// ---------------------------------------------------------------------------
// K3: offset conv as split-tf32 implicit GEMM.
// BM=128 (2 y-rows of one image), BN=32 (27 used), BK=32.
// A gather = shifted-window read of x (1 predicated LDG/value), hi/lo split.
// smem: A 2buf x (16K hi + 16K lo) @0 | B 4 stages x (4K hi + 4K lo) @65536
// ---------------------------------------------------------------------------
#define OSM_A 0
#define OSM_B 65536
#define OFF_SMEM 98304

__global__ __launch_bounds__(256, 1) void offset_gemm_kernel(
    const float* __restrict__ x, const float* __restrict__ bias)
{
    extern __shared__ __align__(128) char smem[];
    const uint32_t sbase = smem_u32(smem);
    const int tid = threadIdx.x;
    const int m0 = blockIdx.x * 128;
    const int nimg = m0 >> 12;
    const int y0 = (m0 & 4095) >> 6;

    // ---- B cp.async assignment: 32 rows x 128B, 1 hi + 1 lo chunk/thread ----
    const int ldrow = tid >> 3;          // 0..31
    const int ldcol = tid & 7;
    const int swzb  = ldcol ^ (ldrow & 7);
    const char* gBh = (const char*)(g_wOffHi + (size_t)ldrow * KDIM) + ldcol * 16;
    const char* gBl = (const char*)(g_wOffLo + (size_t)ldrow * KDIM) + ldcol * 16;
    const uint32_t dBh = sbase + OSM_B + ldrow * 128 + swzb * 16;

#define LOAD_OB(tt_) do {                                                     \
    uint32_t so_ = ((tt_) & 3) * 8192;                                        \
    size_t   ko_ = (size_t)(tt_) * 128;                                       \
    cp_async16(dBh + so_, gBh + ko_);                                         \
    cp_async16(dBh + so_ + 4096, gBl + ko_);                                  \
} while (0)

    LOAD_OB(0); asm volatile("cp.async.commit_group;" ::: "memory");
    LOAD_OB(1); asm volatile("cp.async.commit_group;" ::: "memory");
    LOAD_OB(2); asm volatile("cp.async.commit_group;" ::: "memory");

    const int mloc = tid & 127;
    const int half = tid >> 7;
    const int lane = tid & 31, warp = tid >> 5;
    const int g  = lane >> 2, tg = lane & 3;
    const int wm = warp * 16;

    const float* xn = x + (size_t)nimg * CC * 4096;

    float c[4][4];
#pragma unroll
    for (int i = 0; i < 4; i++)
#pragma unroll
        for (int r = 0; r < 4; r++) c[i][r] = 0.f;

    int soff = 0;
    bool valid = false;

    for (int t = 0; t < NTILES; t++) {
        if ((t & 7) == 0) {
            int kk = t >> 3;
            int yy = y0 + (mloc >> 6) + kk / 3 - 1;
            int xx = (mloc & 63) + (kk % 3) - 1;
            valid = ((unsigned)yy < 64u) && ((unsigned)xx < 64u);
            soff = yy * 64 + xx;
        }

        // ---- gather A(t): shifted window, split hi/lo, permuted, swizzled ----
        {
            const int c0 = (t & 7) * 32;
            const float* xp = xn + (size_t)c0 * 4096;
            const uint32_t Awh = sbase + OSM_A + (t & 1) * 32768 + mloc * 128;
#pragma unroll
            for (int p8 = 0; p8 < 2; p8++) {
#pragma unroll
                for (int q = 0; q < 4; q++) {
                    int ct = half * 16 + p8 * 8 + q;
                    float v0 = valid ? __ldg(xp + (size_t)ct * 4096 + soff) : 0.f;
                    float v1 = valid ? __ldg(xp + (size_t)(ct + 4) * 4096 + soff) : 0.f;
                    float h0 = to_tf32(v0), l0 = to_tf32(v0 - h0);
                    float h1 = to_tf32(v1), l1 = to_tf32(v1 - h1);
                    int cp = (ct & 0x18) | (q << 1);
                    uint32_t off = ((((uint32_t)cp >> 2) ^ (mloc & 7)) << 4)
                                 + ((cp & 3) << 2);
                    asm volatile("st.shared.v2.b32 [%0], {%1,%2};"
                                 :: "r"(Awh + off),
                                    "r"(__float_as_uint(h0)), "r"(__float_as_uint(h1))
                                 : "memory");
                    asm volatile("st.shared.v2.b32 [%0], {%1,%2};"
                                 :: "r"(Awh + 16384 + off),
                                    "r"(__float_as_uint(l0)), "r"(__float_as_uint(l1))
                                 : "memory");
                }
            }
        }

        asm volatile("cp.async.wait_group 2;" ::: "memory");
        __syncthreads();
        if (t + 3 < NTILES) LOAD_OB(t + 3);
        asm volatile("cp.async.commit_group;" ::: "memory");

        const uint32_t As = sbase + OSM_A + (t & 1) * 32768;
        const uint32_t Bs = sbase + OSM_B + (t & 3) * 8192;

#pragma unroll
        for (int ks = 0; ks < 4; ks++) {
            const int ch = ks * 2 + (tg >> 1);
            const int hb = (tg & 1) << 3;

            uint32_t ah[4], al[4];
            {
                int r1 = wm + g, r2 = r1 + 8;
                uint32_t ad1 = As + r1 * 128 + ((ch ^ (r1 & 7)) << 4) + hb;
                uint32_t ad2 = As + r2 * 128 + ((ch ^ (r2 & 7)) << 4) + hb;
                asm volatile("ld.shared.v2.b32 {%0,%1}, [%2];"
                             : "=r"(ah[0]), "=r"(ah[2]) : "r"(ad1));
                asm volatile("ld.shared.v2.b32 {%0,%1}, [%2];"
                             : "=r"(ah[1]), "=r"(ah[3]) : "r"(ad2));
                asm volatile("ld.shared.v2.b32 {%0,%1}, [%2];"
                             : "=r"(al[0]), "=r"(al[2]) : "r"(ad1 + 16384));
                asm volatile("ld.shared.v2.b32 {%0,%1}, [%2];"
                             : "=r"(al[1]), "=r"(al[3]) : "r"(ad2 + 16384));
            }
            uint32_t bh[4][2], bl[4][2];
#pragma unroll
            for (int nt = 0; nt < 4; nt++) {
                int rr = nt * 8 + g;
                uint32_t bd = Bs + rr * 128 + ((ch ^ (rr & 7)) << 4) + hb;
                asm volatile("ld.shared.v2.b32 {%0,%1}, [%2];"
                             : "=r"(bh[nt][0]), "=r"(bh[nt][1]) : "r"(bd));
                asm volatile("ld.shared.v2.b32 {%0,%1}, [%2];"
                             : "=r"(bl[nt][0]), "=r"(bl[nt][1]) : "r"(bd + 4096));
            }
#pragma unroll
            for (int nt = 0; nt < 4; nt++) {
                MMA_TF32(c[nt], ah, bh[nt]);
                MMA_TF32(c[nt], ah, bl[nt]);
                MMA_TF32(c[nt], al, bh[nt]);
            }
        }
    }

    // ---- epilogue: write g_om[n][oc][y][x] (+bias), oc < 27 only ----
    float* ob = g_om + (size_t)nimg * 27 * 4096 + (m0 & 4095);
    int lm = wm + g;
#pragma unroll
    for (int nt = 0; nt < 4; nt++) {
        int oc0 = nt * 8 + tg * 2;
        if (oc0 < 27) {
            float bb = bias[oc0];
            ob[(size_t)oc0 * 4096 + lm]     = c[nt][0] + bb;
            ob[(size_t)oc0 * 4096 + lm + 8] = c[nt][2] + bb;
        }
        if (oc0 + 1 < 27) {
            float bb = bias[oc0 + 1];
            ob[(size_t)(oc0 + 1) * 4096 + lm]     = c[nt][1] + bb;
            ob[(size_t)(oc0 + 1) * 4096 + lm + 8] = c[nt][3] + bb;
        }
    }
}

// ---------------------------------------------------------------------------
// K4: FUSED deformable-sample + tf32 GEMM (unchanged from R7 — passing)
// BM=128, BN=256, BK=32.
// smem: A dbl-buf 2x16KB @0 | B 4-stage 4x32KB @32768 | metadata @163840
// ---------------------------------------------------------------------------
#define SM_A    0
#define SM_B    32768
#define SM_MOFF 163840
#define SM_MWT  182272
#define FUSED_SMEM 200704

__global__ __launch_bounds__(256, 1) void fused_gemm_kernel(
    const float* __restrict__ x, float* __restrict__ out)
{
    extern __shared__ __align__(128) char smem[];
    const uint32_t sbase = smem_u32(smem);
    const int tid = threadIdx.x;
    const int m0 = blockIdx.x * 128;
    const int nimg = m0 >> 12;
    const int y0 = (m0 & 4095) >> 6;

    int4*   moff = (int4*)(smem + SM_MOFF);
    float4* mwt  = (float4*)(smem + SM_MWT);

    const int ldrow = tid >> 3;
    const int ldcol = tid & 7;
    const int swzb  = ldcol ^ (ldrow & 7);
    const char* gB0 = (const char*)(g_wB + (size_t)ldrow * KDIM) + ldcol * 16;
    const uint32_t dB0 = sbase + SM_B + ldrow * 128 + swzb * 16;

#define LOAD_B(tt_) do {                                                      \
    uint32_t so_ = ((tt_) & 3) * 32768;                                       \
    size_t   ko_ = (size_t)(tt_) * 128;                                       \
    _Pragma("unroll")                                                         \
    for (int i_ = 0; i_ < 8; i_++)                                            \
        cp_async16(dB0 + so_ + i_ * 4096,                                     \
                   gB0 + ko_ + (size_t)i_ * 32 * KDIM * 4);                   \
} while (0)

    LOAD_B(0); asm volatile("cp.async.commit_group;" ::: "memory");
    LOAD_B(1); asm volatile("cp.async.commit_group;" ::: "memory");
    LOAD_B(2); asm volatile("cp.async.commit_group;" ::: "memory");

    for (int idx = tid; idx < 1152; idx += 256) {
        int p128 = idx / 9, kk = idx - p128 * 9;
        int yy = y0 + (p128 >> 6);
        int xx = p128 & 63;
        const float* omn = g_om + (size_t)nimg * 27 * 4096 + yy * 64 + xx;
        float oy = omn[(size_t)(2 * kk) * 4096];
        float ox = omn[(size_t)(2 * kk + 1) * 4096];
        float mv = omn[(size_t)(18 + kk) * 4096];
        float m  = 1.f / (1.f + __expf(-mv));

        float py = (float)(yy + kk / 3) + oy;
        float px = (float)(xx + (kk % 3)) + ox;
        py = fminf(fmaxf(py, 0.f), 65.f);
        px = fminf(fmaxf(px, 0.f), 65.f);
        float fy = floorf(py), fx = floorf(px);
        int y1 = (int)fy, x1 = (int)fx;
        float ly = py - fy, lx = px - fx;
        float hy = 1.f - ly, hx = 1.f - lx;
        float wq[4] = { hy * hx, hy * lx, ly * hx, ly * lx };

        int4 o4; float4 w4;
        int   ov[4]; float wv[4];
#pragma unroll
        for (int q = 0; q < 4; q++) {
            int Y = y1 + (q >> 1);
            int X = x1 + (q & 1);
            bool valid = (Y >= 1 && Y <= 64 && X >= 1 && X <= 64);
            int Yc = min(max(Y, 1), 64), Xc = min(max(X, 1), 64);
            ov[q] = (Yc - 1) * 64 + (Xc - 1);
            wv[q] = valid ? wq[q] * m : 0.f;
        }
        o4.x = ov[0]; o4.y = ov[1]; o4.z = ov[2]; o4.w = ov[3];
        w4.x = wv[0]; w4.y = wv[1]; w4.z = wv[2]; w4.w = wv[3];
        moff[idx] = o4;
        mwt[idx]  = w4;
    }
    __syncthreads();

    const int mloc = tid & 127;
    const int half = tid >> 7;
    const int lane = tid & 31, warp = tid >> 5;
    const int g  = lane >> 2, tg = lane & 3;
    const int wm = (warp >> 2) * 64;
    const int wn = (warp & 3) * 64;

    const float* xn = x + (size_t)nimg * CC * 4096;

    float c[4][8][4];
#pragma unroll
    for (int i = 0; i < 4; i++)
#pragma unroll
        for (int j = 0; j < 8; j++)
#pragma unroll
            for (int r = 0; r < 4; r++) c[i][j][r] = 0.f;

    int   ro[4];
    float rw[4];

    for (int t = 0; t < NTILES; t++) {
        if ((t & 7) == 0) {
            int kk = t >> 3;
            int4   o4 = moff[mloc * 9 + kk];
            float4 w4 = mwt [mloc * 9 + kk];
            ro[0] = o4.x; ro[1] = o4.y; ro[2] = o4.z; ro[3] = o4.w;
            rw[0] = w4.x; rw[1] = w4.y; rw[2] = w4.z; rw[3] = w4.w;
        }

        {
            const int c0 = (t & 7) * 32;
            const float* xp = xn + (size_t)c0 * 4096;
            const uint32_t Aw = sbase + SM_A + (t & 1) * 16384 + mloc * 128;
#pragma unroll
            for (int p8 = 0; p8 < 2; p8++) {
#pragma unroll
                for (int q = 0; q < 4; q++) {
                    int ct = half * 16 + p8 * 8 + q;
                    const float* plo = xp + (size_t)ct * 4096;
                    const float* phi = plo + 4 * 4096;
                    float vlo = rw[0] * __ldg(&plo[ro[0]])
                              + rw[1] * __ldg(&plo[ro[1]])
                              + rw[2] * __ldg(&plo[ro[2]])
                              + rw[3] * __ldg(&plo[ro[3]]);
                    float vhi = rw[0] * __ldg(&phi[ro[0]])
                              + rw[1] * __ldg(&phi[ro[1]])
                              + rw[2] * __ldg(&phi[ro[2]])
                              + rw[3] * __ldg(&phi[ro[3]]);
                    int cp = (ct & 0x18) | (q << 1);
                    uint32_t chunk = cp >> 2;
                    uint32_t addr = Aw + ((chunk ^ (mloc & 7)) << 4)
                                  + ((cp & 3) << 2);
                    uint32_t rlo = __float_as_uint(to_tf32(vlo));
                    uint32_t rhi = __float_as_uint(to_tf32(vhi));
                    asm volatile("st.shared.v2.b32 [%0], {%1,%2};"
                                 :: "r"(addr), "r"(rlo), "r"(rhi) : "memory");
                }
            }
        }

        asm volatile("cp.async.wait_group 2;" ::: "memory");
        __syncthreads();

        if (t + 3 < NTILES) LOAD_B(t + 3);
        asm volatile("cp.async.commit_group;" ::: "memory");

        const uint32_t As = sbase + SM_A + (t & 1) * 16384;
        const uint32_t Bs = sbase + SM_B + (t & 3) * 32768;

#pragma unroll
        for (int ks = 0; ks < 4; ks++) {
            const int ch = ks * 2 + (tg >> 1);
            const int hb = (tg & 1) << 3;

            uint32_t a[4][4];
#pragma unroll
            for (int mt = 0; mt < 4; mt++) {
                int r1 = wm + mt * 16 + g;
                int r2 = r1 + 8;
                uint32_t ad1 = As + r1 * 128 + ((ch ^ (r1 & 7)) << 4) + hb;
                uint32_t ad2 = As + r2 * 128 + ((ch ^ (r2 & 7)) << 4) + hb;
                asm volatile("ld.shared.v2.b32 {%0,%1}, [%2];"
                             : "=r"(a[mt][0]), "=r"(a[mt][2]) : "r"(ad1));
                asm volatile("ld.shared.v2.b32 {%0,%1}, [%2];"
                             : "=r"(a[mt][1]), "=r"(a[mt][3]) : "r"(ad2));
            }
            uint32_t b[8][2];
#pragma unroll
            for (int nt = 0; nt < 8; nt++) {
                int rr = wn + nt * 8 + g;
                uint32_t bd = Bs + rr * 128 + ((ch ^ (rr & 7)) << 4) + hb;
                asm volatile("ld.shared.v2.b32 {%0,%1}, [%2];"
                             : "=r"(b[nt][0]), "=r"(b[nt][1]) : "r"(bd));
            }
#pragma unroll
            for (int mt = 0; mt < 4; mt++)
#pragma unroll
                for (int nt = 0; nt < 8; nt++)
                    MMA_TF32(c[mt][nt], a[mt], b[nt]);
        }
    }

    float* ob = out + (size_t)nimg * OC * 4096 + (m0 & 4095);
#pragma unroll
    for (int mt = 0; mt < 4; mt++) {
        int lm = wm + mt * 16 + g;
#pragma unroll
        for (int nt = 0; nt < 8; nt++) {
            int o = wn + nt * 8 + tg * 2;
            ob[(size_t)o * 4096 + lm]           = c[mt][nt][0];
            ob[(size_t)(o + 1) * 4096 + lm]     = c[mt][nt][1];
            ob[(size_t)o * 4096 + lm + 8]       = c[mt][nt][2];
            ob[(size_t)(o + 1) * 4096 + lm + 8] = c[mt][nt][3];
        }
    }
}

// ---------------------------------------------------------------------------
extern "C" void kernel_launch(void* const* d_in, const int* in_sizes, int n_in,
                              void* d_out, int out_size)
{
    const float* x      = (const float*)d_in[0];
    const float* conv_w = (const float*)d_in[1];
    const float* conv_b = (const float*)d_in[2];
    const float* dcn_w  = (const float*)d_in[3];
    float* out = (float*)d_out;

    cudaFuncSetAttribute(offset_gemm_kernel,
                         cudaFuncAttributeMaxDynamicSharedMemorySize, OFF_SMEM);
    cudaFuncSetAttribute(fused_gemm_kernel,
                         cudaFuncAttributeMaxDynamicSharedMemorySize, FUSED_SMEM);

    permute_w_kernel<<<OC, 256>>>(dcn_w);
    permute_woff_kernel<<<32, 256>>>(conv_w);
    offset_gemm_kernel<<<MDIM / 128, 256, OFF_SMEM>>>(x, conv_b);
    fused_gemm_kernel<<<MDIM / 128, 256, FUSED_SMEM>>>(x, out);
}